// round 13
// baseline (speedup 1.0000x reference)
#include <cuda_runtime.h>
#include <math.h>

// Problem constants
#define NB 32     // batch
#define SS 12     // seq len
#define FF 128    // features
#define KH 8      // heads
#define HH 64     // head dim
#define CC 64     // out channels
#define NN 512    // nodes
#define SEGS 8    // n-segments per c2 (512/8 = 64 rows/segment, 16 KB)

#define K1_BLOCKS (NB + 1)        // 32 feature blocks + 1 out-init block
#define K2_BLOCKS (CC * SEGS)     // 512 stream blocks

// Scratch (no allocations allowed)
__device__ float g_v[NB * CC];    // per-batch feature vector v[b][c]

// ---------------------------------------------------------------------------
// K1 (PDL primary, tiny): features + output init. Grid = 33 blocks x 256 thr.
//   blocks 0..31: v[b][c] = sum_j elu( x_last[b] . W_heads[:,:,j] ) * W_out[j][c]
//   block  32:    out[b][c2] = bf[c2]   (accumulation base for K2's atomics)
// ---------------------------------------------------------------------------
__global__ void __launch_bounds__(256) k1_features(
    const float* __restrict__ x,
    const float* __restrict__ W_heads,
    const float* __restrict__ W_out,
    const float* __restrict__ bf,
    float* __restrict__ out)
{
    __shared__ __align__(16) float sbuf[128 + 2048 + 512 + 256];
    int bid = blockIdx.x;
    int tid = threadIdx.x;

    if (bid == NB) {
        // ---- init out with bias ----
        #pragma unroll
        for (int i = 0; i < (NB * CC) / 256; ++i) {
            int idx = tid + i * 256;
            out[idx] = bf[idx & (CC - 1)];
        }
        return;
    }

    int b = bid;
    float* xl    = sbuf;                 // 128
    float* hpart = sbuf + 128;           // [4 fparts][512 j]
    float* hp    = sbuf + 128 + 2048;    // 512
    float* red   = sbuf + 128 + 2048 + 512; // 256

    if (tid < 32)
        ((float4*)xl)[tid] = ((const float4*)(x + b * SS * FF + (SS - 1) * FF))[tid];
    __syncthreads();

    // hp partials: 512 slots = 4 f-partitions x 128 j-quads, 2 slots/thread
    #pragma unroll
    for (int s = 0; s < 2; ++s) {
        int slot  = tid + s * 256;       // 0..511
        int fpart = slot >> 7;           // 0..3
        int jq    = slot & 127;          // j-quad
        int k     = jq >> 4;             // head index
        int h0    = (jq & 15) * 4;
        const float4* w = (const float4*)(W_heads + (size_t)k * FF * HH + h0);
        int f0 = fpart * 32;
        float4 acc = make_float4(0.f, 0.f, 0.f, 0.f);
        #pragma unroll 8
        for (int i = 0; i < 32; ++i) {
            float4 wv = w[(f0 + i) * 16];
            float xv = xl[f0 + i];
            acc.x = fmaf(xv, wv.x, acc.x);
            acc.y = fmaf(xv, wv.y, acc.y);
            acc.z = fmaf(xv, wv.z, acc.z);
            acc.w = fmaf(xv, wv.w, acc.w);
        }
        ((float4*)hpart)[fpart * 128 + jq] = acc;
    }
    __syncthreads();

    // reduce f-partitions + elu
    #pragma unroll
    for (int s = 0; s < 2; ++s) {
        int j = tid + s * 256;
        float sum = (hpart[j] + hpart[512 + j]) + (hpart[1024 + j] + hpart[1536 + j]);
        hp[j] = (sum > 0.f) ? sum : expm1f(sum);   // elu (alpha=1)
    }
    __syncthreads();

    // v[c] = sum_j hp[j]*W_out[j][c]
    {
        int c = tid & 63;
        int part = tid >> 6;
        int j0 = part * 128;
        float acc0 = 0.f, acc1 = 0.f;
        #pragma unroll 16
        for (int j = 0; j < 64; ++j) {
            acc0 = fmaf(hp[j0 + j],      W_out[(j0 + j) * CC + c],      acc0);
            acc1 = fmaf(hp[j0 + 64 + j], W_out[(j0 + 64 + j) * CC + c], acc1);
        }
        red[part * 64 + c] = acc0 + acc1;
    }
    __syncthreads();
    #pragma unroll
    for (int s = 2; s >= 1; s >>= 1) {
        int c = tid & 63;
        int part = tid >> 6;
        if (part < s) red[part * 64 + c] += red[(part + s) * 64 + c];
        __syncthreads();
    }
    if (tid < CC) g_v[b * CC + tid] = red[tid];
}

// ---------------------------------------------------------------------------
// K2 (PDL secondary): stream + distributed finale. Grid = 512 blocks (c2,seg).
// Phase A (K1-independent): part[c] = sum_{n in seg} Wf[c2][n*64+c]  (16 KB)
// cudaGridDependencySynchronize()  -- K1 (33 blocks) long done by now
// Phase B: for each b: atomicAdd(out[b][c2], dot(v[b], part))
// ---------------------------------------------------------------------------
__global__ void __launch_bounds__(256) k2_stream(
    const float* __restrict__ Wf,
    float* __restrict__ out)
{
    __shared__ __align__(16) float4 sred[16 * 16];   // [group][lane] tree reduce
    __shared__ __align__(16) float4 sv4[NB * 16];    // all v

    int bid  = blockIdx.x;
    int c2   = bid >> 3;          // 0..63
    int seg  = bid & 7;           // 0..7
    int tid  = threadIdx.x;
    int lane = tid & 15;          // float4 index within 64-float row
    int g    = tid >> 4;          // 0..15 row-groups (4 rows each)

    // ---- Phase A: stream this (c2, seg) slice ----
    const float4* base = (const float4*)(Wf + (size_t)c2 * (NN * CC));
    int n0 = seg * 64 + g * 4;
    float4 v0 = base[(n0 + 0) * 16 + lane];
    float4 v1 = base[(n0 + 1) * 16 + lane];
    float4 v2 = base[(n0 + 2) * 16 + lane];
    float4 v3 = base[(n0 + 3) * 16 + lane];
    float4 acc;
    acc.x = (v0.x + v1.x) + (v2.x + v3.x);
    acc.y = (v0.y + v1.y) + (v2.y + v3.y);
    acc.z = (v0.z + v1.z) + (v2.z + v3.z);
    acc.w = (v0.w + v1.w) + (v2.w + v3.w);
    sred[g * 16 + lane] = acc;
    __syncthreads();

    #pragma unroll
    for (int s = 8; s >= 1; s >>= 1) {
        if (g < s) {
            float4 o = sred[(g + s) * 16 + lane];
            float4 m = sred[g * 16 + lane];
            m.x += o.x; m.y += o.y; m.z += o.z; m.w += o.w;
            sred[g * 16 + lane] = m;
        }
        __syncthreads();
    }
    // part row now in sred[0..15]

    // ---- wait for K1 (v + out-init) ----
    cudaGridDependencySynchronize();

    // load all v: 512 float4, 2/thread (L2-hot, broadcast across blocks)
    sv4[tid]       = ((const float4*)g_v)[tid];
    sv4[tid + 256] = ((const float4*)g_v)[tid + 256];
    __syncthreads();

    // ---- Phase B: per-batch dot + atomic accumulate ----
    // tid -> b = tid/8 (0..31), part = tid%8 (2 float4 of c each)
    {
        int b = tid >> 3;
        int part = tid & 7;
        float4 a0 = sv4[b * 16 + part * 2 + 0];
        float4 a1 = sv4[b * 16 + part * 2 + 1];
        float4 w0 = sred[part * 2 + 0];
        float4 w1 = sred[part * 2 + 1];
        float d = fmaf(a0.x, w0.x, fmaf(a0.y, w0.y, fmaf(a0.z, w0.z, a0.w * w0.w)));
        d = fmaf(a1.x, w1.x, fmaf(a1.y, w1.y, fmaf(a1.z, w1.z, fmaf(a1.w, w1.w, d))));
        d += __shfl_xor_sync(0xffffffffu, d, 1);
        d += __shfl_xor_sync(0xffffffffu, d, 2);
        d += __shfl_xor_sync(0xffffffffu, d, 4);
        if (part == 0)
            atomicAdd(&out[b * CC + c2], d);
    }
}

// ---------------------------------------------------------------------------
// Inputs (metadata order):
//   0: x        (32,12,128)   f32
//   1: W_heads  (8,128,64)    f32
//   2: a1_heads (8,64)        f32   (unused: softmax over identical rows is uniform)
//   3: a2_heads (8,64)        f32   (unused)
//   4: W_out    (512,64)      f32
//   5: a1_out   (64)          f32   (unused)
//   6: a2_out   (64)          f32   (unused)
//   7: Wf       (64,32768)    f32
//   8: bf       (64)          f32
// Output: (32,64) f32
// ---------------------------------------------------------------------------
extern "C" void kernel_launch(void* const* d_in, const int* in_sizes, int n_in,
                              void* d_out, int out_size)
{
    const float* x       = (const float*)d_in[0];
    const float* W_heads = (const float*)d_in[1];
    const float* W_out   = (const float*)d_in[4];
    const float* Wf      = (const float*)d_in[7];
    const float* bf      = (const float*)d_in[8];
    float* out = (float*)d_out;

    // K1: tiny primary (33 blocks) — features + out<-bf init.
    k1_features<<<K1_BLOCKS, 256>>>(x, W_heads, W_out, bf, out);

    // K2: PDL secondary — streams Wf while K1 runs; per-block finale gated
    // by cudaGridDependencySynchronize().
    cudaLaunchConfig_t cfg = {};
    cfg.gridDim = dim3(K2_BLOCKS);
    cfg.blockDim = dim3(256);
    cfg.dynamicSmemBytes = 0;
    cfg.stream = 0;
    cudaLaunchAttribute attrs[1];
    attrs[0].id = cudaLaunchAttributeProgrammaticStreamSerialization;
    attrs[0].val.programmaticStreamSerializationAllowed = 1;
    cfg.attrs = attrs;
    cfg.numAttrs = 1;
    cudaLaunchKernelEx(&cfg, k2_stream, Wf, out);
}